// round 8
// baseline (speedup 1.0000x reference)
#include <cuda_runtime.h>
#include <cstdint>

#define B_ 64
#define S_ 2048
#define D_ 512
#define U_ 512
#define M_TOTAL (B_ * S_)
#define CTX_SPLIT 8

typedef unsigned long long u64;

// ---------------- scratch (no allocations allowed) ----------------
__device__ float g_base[B_ * U_];                 // Ws@h + bs + bh + bc
__device__ float g_score[M_TOTAL];                // pre-softmax scores
__device__ float g_attn[M_TOTAL];                 // attention weights
__device__ float g_ctxpart[B_ * CTX_SPLIT * D_];  // partial contexts

// ---------------- packed f32x2 helpers (sm_100-family PTX; FFMA2 in SASS) ----------------
__device__ __forceinline__ u64 pack2(float x, float y) {
    u64 d;
    unsigned lo = __float_as_uint(x), hi = __float_as_uint(y);
    asm("mov.b64 %0, {%1, %2};" : "=l"(d) : "r"(lo), "r"(hi));
    return d;
}
__device__ __forceinline__ void unpack2(u64 d, float& x, float& y) {
    unsigned lo, hi;
    asm("mov.b64 {%0, %1}, %2;" : "=r"(lo), "=r"(hi) : "l"(d));
    x = __uint_as_float(lo);
    y = __uint_as_float(hi);
}
#define FFMA2(d, a, b, c) \
    asm("fma.rn.f32x2 %0, %1, %2, %3;" : "=l"(d) : "l"(a), "l"(b), "l"(c))

// ---------------- K1: base[b,u] = dec_hidden[b]@Ws[:,u] + bs+bh+bc ----------------
__global__ void k1_base(const float* __restrict__ dec,
                        const float* __restrict__ Ws,
                        const float* __restrict__ bs,
                        const float* __restrict__ bh,
                        const float* __restrict__ bc)
{
    const int b = blockIdx.x;       // 64 blocks
    const int u = threadIdx.x;      // 512 threads
    const float* dh = dec + b * D_;
    float acc = 0.f;
    #pragma unroll 8
    for (int d = 0; d < D_; ++d)
        acc = fmaf(dh[d], Ws[d * U_ + u], acc);   // Ws read coalesced across u
    g_base[b * U_ + u] = acc + bs[u] + bh[u] + bc[u];
}

// ---------------- K2: fused GEMM(enc@Wh) + tanh + Vw-reduction -> score ----------------
// M=131072, N=512, K=512. Tile BM=128, BN=128, BK=32, microtile 8x8, 256 threads.
// Double-buffered smem + register prefetch; inner product via packed fma.rn.f32x2.
#define BM 128
#define BN 128
#define BK 32
#define TM 8
#define TN 8

#define AS_STRIDE 132                           // BM+4: even & 16B-aligned rows
#define AS_TILE   (BK * AS_STRIDE)              // floats per A buffer
#define BS_TILE   (BK * BN)                     // floats per B buffer
#define K2_SMEM_FLOATS (2 * AS_TILE + 2 * BS_TILE)
#define K2_SMEM_BYTES  (K2_SMEM_FLOATS * 4)     // 66560 B

__global__ __launch_bounds__(256) void k2_score(
    const float* __restrict__ enc,   // (B*S, D)
    const float* __restrict__ Wh,    // (D, U)
    const float* __restrict__ Wc,    // (1, U)
    const float* __restrict__ Vw,    // (U, 1)
    const float* __restrict__ pcov)  // (B*S)
{
    extern __shared__ float smem[];
    float* As = smem;                // [2][BK][AS_STRIDE], k-major transposed A
    float* Bs = smem + 2 * AS_TILE;  // [2][BK][BN], k-major Wh tile

    const int tid = threadIdx.x;
    const int tx = tid & 15;          // 0..15 -> N
    const int ty = tid >> 4;          // 0..15 -> M
    const int row0 = blockIdx.x * BM; // 1024 blocks; BM | S so whole block is one batch b
    const int b = row0 / S_;

    float4 ra[4], rb[4];

    float pc[TM];
    #pragma unroll
    for (int i = 0; i < TM; ++i) pc[i] = pcov[row0 + ty * TM + i];

    float sc[TM];
    #pragma unroll
    for (int i = 0; i < TM; ++i) sc[i] = 0.f;

    for (int nc = 0; nc < U_; nc += BN) {
        u64 acc2[TM][TN / 2];          // packed (col 2j, 2j+1)
        const u64 z2 = pack2(0.f, 0.f);
        #pragma unroll
        for (int i = 0; i < TM; ++i)
            #pragma unroll
            for (int j = 0; j < TN / 2; ++j) acc2[i][j] = z2;

        // ---- prologue: fetch k-tile 0 into regs, stage into buffer 0 ----
        #pragma unroll
        for (int l = 0; l < 4; ++l) {
            int f  = tid + l * 256;
            int r  = f >> 3;          // A row within tile
            int c4 = f & 7;           // A float4 index along k
            ra[l] = *(const float4*)(enc + (size_t)(row0 + r) * D_ + c4 * 4);
            int rk = f >> 5;          // B k-row
            int n4 = f & 31;          // B float4 index along n
            rb[l] = *(const float4*)(Wh + (size_t)rk * U_ + nc + n4 * 4);
        }
        #pragma unroll
        for (int l = 0; l < 4; ++l) {
            int f  = tid + l * 256;
            int r  = f >> 3;
            int c4 = f & 7;
            As[(c4 * 4 + 0) * AS_STRIDE + r] = ra[l].x;
            As[(c4 * 4 + 1) * AS_STRIDE + r] = ra[l].y;
            As[(c4 * 4 + 2) * AS_STRIDE + r] = ra[l].z;
            As[(c4 * 4 + 3) * AS_STRIDE + r] = ra[l].w;
            int rk = f >> 5;
            int n4 = f & 31;
            *(float4*)&Bs[rk * BN + n4 * 4] = rb[l];
        }
        __syncthreads();

        int p = 0;
        for (int k0 = BK; k0 < D_; k0 += BK) {
            // issue next tile's global loads early (latency hidden by compute)
            #pragma unroll
            for (int l = 0; l < 4; ++l) {
                int f  = tid + l * 256;
                int r  = f >> 3;
                int c4 = f & 7;
                ra[l] = *(const float4*)(enc + (size_t)(row0 + r) * D_ + k0 + c4 * 4);
                int rk = f >> 5;
                int n4 = f & 31;
                rb[l] = *(const float4*)(Wh + (size_t)(k0 + rk) * U_ + nc + n4 * 4);
            }

            // compute on current buffer p (packed f32x2 FMA)
            const float* Ap = As + p * AS_TILE;
            const float* Bp = Bs + p * BS_TILE;
            #pragma unroll
            for (int k = 0; k < BK; ++k) {
                float4 av0 = *(const float4*)&Ap[k * AS_STRIDE + ty * TM];
                float4 av1 = *(const float4*)&Ap[k * AS_STRIDE + ty * TM + 4];
                float4 bv0 = *(const float4*)&Bp[k * BN + tx * TN];
                float4 bv1 = *(const float4*)&Bp[k * BN + tx * TN + 4];
                u64 aa[TM], bb[TN / 2];
                aa[0] = pack2(av0.x, av0.x); aa[1] = pack2(av0.y, av0.y);
                aa[2] = pack2(av0.z, av0.z); aa[3] = pack2(av0.w, av0.w);
                aa[4] = pack2(av1.x, av1.x); aa[5] = pack2(av1.y, av1.y);
                aa[6] = pack2(av1.z, av1.z); aa[7] = pack2(av1.w, av1.w);
                bb[0] = pack2(bv0.x, bv0.y); bb[1] = pack2(bv0.z, bv0.w);
                bb[2] = pack2(bv1.x, bv1.y); bb[3] = pack2(bv1.z, bv1.w);
                #pragma unroll
                for (int i = 0; i < TM; ++i)
                    #pragma unroll
                    for (int j = 0; j < TN / 2; ++j)
                        FFMA2(acc2[i][j], aa[i], bb[j], acc2[i][j]);
            }

            // stage next tile into the other buffer; single barrier per k-tile
            float* An = As + (p ^ 1) * AS_TILE;
            float* Bn = Bs + (p ^ 1) * BS_TILE;
            #pragma unroll
            for (int l = 0; l < 4; ++l) {
                int f  = tid + l * 256;
                int r  = f >> 3;
                int c4 = f & 7;
                An[(c4 * 4 + 0) * AS_STRIDE + r] = ra[l].x;
                An[(c4 * 4 + 1) * AS_STRIDE + r] = ra[l].y;
                An[(c4 * 4 + 2) * AS_STRIDE + r] = ra[l].z;
                An[(c4 * 4 + 3) * AS_STRIDE + r] = ra[l].w;
                int rk = f >> 5;
                int n4 = f & 31;
                *(float4*)&Bn[rk * BN + n4 * 4] = rb[l];
            }
            __syncthreads();
            p ^= 1;
        }

        // tail compute on final buffer
        {
            const float* Ap = As + p * AS_TILE;
            const float* Bp = Bs + p * BS_TILE;
            #pragma unroll
            for (int k = 0; k < BK; ++k) {
                float4 av0 = *(const float4*)&Ap[k * AS_STRIDE + ty * TM];
                float4 av1 = *(const float4*)&Ap[k * AS_STRIDE + ty * TM + 4];
                float4 bv0 = *(const float4*)&Bp[k * BN + tx * TN];
                float4 bv1 = *(const float4*)&Bp[k * BN + tx * TN + 4];
                u64 aa[TM], bb[TN / 2];
                aa[0] = pack2(av0.x, av0.x); aa[1] = pack2(av0.y, av0.y);
                aa[2] = pack2(av0.z, av0.z); aa[3] = pack2(av0.w, av0.w);
                aa[4] = pack2(av1.x, av1.x); aa[5] = pack2(av1.y, av1.y);
                aa[6] = pack2(av1.z, av1.z); aa[7] = pack2(av1.w, av1.w);
                bb[0] = pack2(bv0.x, bv0.y); bb[1] = pack2(bv0.z, bv0.w);
                bb[2] = pack2(bv1.x, bv1.y); bb[3] = pack2(bv1.z, bv1.w);
                #pragma unroll
                for (int i = 0; i < TM; ++i)
                    #pragma unroll
                    for (int j = 0; j < TN / 2; ++j)
                        FFMA2(acc2[i][j], aa[i], bb[j], acc2[i][j]);
            }
        }
        // no barrier needed before next nc prologue store: last in-loop
        // __syncthreads already separated compute on buffer 0 from new stores.

        // epilogue for this N-chunk: tanh + Vw reduction (bv dropped: shift-invariant)
        #pragma unroll
        for (int j = 0; j < TN / 2; ++j) {
            const int u0 = nc + tx * TN + 2 * j;
            const float bb0 = g_base[b * U_ + u0],     bb1 = g_base[b * U_ + u0 + 1];
            const float wc0 = Wc[u0],                  wc1 = Wc[u0 + 1];
            const float vw0 = Vw[u0],                  vw1 = Vw[u0 + 1];
            #pragma unroll
            for (int i = 0; i < TM; ++i) {
                float c0, c1;
                unpack2(acc2[i][j], c0, c1);
                float x0 = c0 + bb0 + pc[i] * wc0;
                float x1 = c1 + bb1 + pc[i] * wc1;
                // tanh(x) = 1 - 2/(exp(2x)+1): 2 MUFU + cheap ops, ~1e-6 abs err
                float t0 = 1.f - __fdividef(2.f, __expf(2.f * x0) + 1.f);
                float t1 = 1.f - __fdividef(2.f, __expf(2.f * x1) + 1.f);
                sc[i] += vw0 * t0 + vw1 * t1;
            }
        }
    }

    // reduce sc across the 16 tx lanes (one 16-lane half of the warp)
    #pragma unroll
    for (int i = 0; i < TM; ++i) {
        float v = sc[i];
        v += __shfl_xor_sync(0xffffffffu, v, 1);
        v += __shfl_xor_sync(0xffffffffu, v, 2);
        v += __shfl_xor_sync(0xffffffffu, v, 4);
        v += __shfl_xor_sync(0xffffffffu, v, 8);
        sc[i] = v;
    }
    if (tx == 0) {
        #pragma unroll
        for (int i = 0; i < TM; ++i)
            g_score[row0 + ty * TM + i] = sc[i];
    }
}

// ---------------- K3: masked renormalized softmax + coverage ----------------
__global__ __launch_bounds__(256) void k3_softmax(
    const float* __restrict__ mask, const float* __restrict__ pcov,
    float* __restrict__ out_attn, float* __restrict__ out_cov)
{
    const int b = blockIdx.x;       // 64
    const int tid = threadIdx.x;    // 256, 8 elems each
    __shared__ float smax[8];
    __shared__ float ssum[8];
    __shared__ float sbc[2];

    float v[8];
    float mx = -3.0e38f;
    #pragma unroll
    for (int i = 0; i < 8; ++i) {
        v[i] = g_score[b * S_ + tid + i * 256];
        mx = fmaxf(mx, v[i]);
    }
    #pragma unroll
    for (int o = 16; o; o >>= 1) mx = fmaxf(mx, __shfl_xor_sync(0xffffffffu, mx, o));
    if ((tid & 31) == 0) smax[tid >> 5] = mx;
    __syncthreads();
    if (tid == 0) {
        float m = smax[0];
        #pragma unroll
        for (int w = 1; w < 8; ++w) m = fmaxf(m, smax[w]);
        sbc[0] = m;
    }
    __syncthreads();
    mx = sbc[0];

    float se = 0.f;
    #pragma unroll
    for (int i = 0; i < 8; ++i) {
        int idx = b * S_ + tid + i * 256;
        v[i] = __expf(v[i] - mx) * mask[idx];   // e_i * m_i; renorm by sum == masked softmax
        se += v[i];
    }
    #pragma unroll
    for (int o = 16; o; o >>= 1) se += __shfl_xor_sync(0xffffffffu, se, o);
    if ((tid & 31) == 0) ssum[tid >> 5] = se;
    __syncthreads();
    if (tid == 0) {
        float s = ssum[0];
        #pragma unroll
        for (int w = 1; w < 8; ++w) s += ssum[w];
        sbc[1] = 1.f / s;
    }
    __syncthreads();
    const float inv = sbc[1];

    #pragma unroll
    for (int i = 0; i < 8; ++i) {
        int idx = b * S_ + tid + i * 256;
        float a = v[i] * inv;
        g_attn[idx]   = a;
        out_attn[idx] = a;
        out_cov[idx]  = a + pcov[idx];
    }
}

// ---------------- K4: partial context over S-chunks ----------------
__global__ __launch_bounds__(128) void k4_ctx(const float* __restrict__ enc)
{
    const int chunk = blockIdx.x;   // 0..7
    const int b = blockIdx.y;       // 0..63
    const int tid = threadIdx.x;    // 128, 4 d's each (float4)
    __shared__ float at[S_ / CTX_SPLIT];   // 256

    const int s0 = chunk * (S_ / CTX_SPLIT);
    for (int i = tid; i < S_ / CTX_SPLIT; i += 128)
        at[i] = g_attn[b * S_ + s0 + i];
    __syncthreads();

    float4 acc = make_float4(0.f, 0.f, 0.f, 0.f);
    const float* base = enc + ((size_t)b * S_ + s0) * D_ + tid * 4;
    #pragma unroll 4
    for (int s = 0; s < S_ / CTX_SPLIT; ++s) {
        float a = at[s];
        float4 e = *(const float4*)(base + (size_t)s * D_);
        acc.x = fmaf(a, e.x, acc.x);
        acc.y = fmaf(a, e.y, acc.y);
        acc.z = fmaf(a, e.z, acc.z);
        acc.w = fmaf(a, e.w, acc.w);
    }
    *(float4*)&g_ctxpart[((size_t)b * CTX_SPLIT + chunk) * D_ + tid * 4] = acc;
}

// ---------------- K5: reduce partial contexts ----------------
__global__ void k5_ctxred(float* __restrict__ out_ctx)
{
    const int b = blockIdx.x;     // 64
    const int d = threadIdx.x;    // 512
    float s = 0.f;
    #pragma unroll
    for (int c = 0; c < CTX_SPLIT; ++c)
        s += g_ctxpart[((size_t)b * CTX_SPLIT + c) * D_ + d];
    out_ctx[b * D_ + d] = s;
}

// ---------------- launcher ----------------
extern "C" void kernel_launch(void* const* d_in, const int* in_sizes, int n_in,
                              void* d_out, int out_size)
{
    const float* dec  = (const float*)d_in[0];   // (B,D)
    const float* enc  = (const float*)d_in[1];   // (B,S,D)
    const float* mask = (const float*)d_in[2];   // (B,S)
    const float* pcov = (const float*)d_in[3];   // (B,S,1)
    const float* Wh   = (const float*)d_in[4];   // (D,U)
    const float* bh   = (const float*)d_in[5];   // (U)
    const float* Ws   = (const float*)d_in[6];   // (D,U)
    const float* bs   = (const float*)d_in[7];   // (U)
    const float* Wc   = (const float*)d_in[8];   // (1,U)
    const float* bc   = (const float*)d_in[9];   // (U)
    const float* Vw   = (const float*)d_in[10];  // (U,1)
    // d_in[11] = bv: shift-invariant under softmax, unused.

    float* out_ctx  = (float*)d_out;                      // (B,D)
    float* out_attn = out_ctx + B_ * D_;                  // (B,S)
    float* out_cov  = out_attn + B_ * S_;                 // (B,S,1)

    // Attribute set (not a stream op, not an alloc): legal during capture,
    // idempotent and deterministic on every call.
    cudaFuncSetAttribute(k2_score, cudaFuncAttributeMaxDynamicSharedMemorySize,
                         K2_SMEM_BYTES);

    k1_base<<<B_, U_>>>(dec, Ws, bs, bh, bc);
    k2_score<<<M_TOTAL / BM, 256, K2_SMEM_BYTES>>>(enc, Wh, Wc, Vw, pcov);
    k3_softmax<<<B_, 256>>>(mask, pcov, out_attn, out_cov);
    k4_ctx<<<dim3(CTX_SPLIT, B_), 128>>>(enc);
    k5_ctxred<<<B_, D_>>>(out_ctx);
}

// round 17
// speedup vs baseline: 1.5505x; 1.5505x over previous
#include <cuda_runtime.h>
#include <cuda_bf16.h>
#include <cstdint>

#define B_ 64
#define S_ 2048
#define D_ 512
#define U_ 512
#define M_TOTAL (B_ * S_)
#define CTX_SPLIT 8

// ---------------- scratch (static __device__: the sanctioned no-alloc path) ----------------
__device__ float g_base[B_ * U_];                  // Ws@h + bs + bh + bc
__device__ float g_score[M_TOTAL];                 // pre-softmax scores
__device__ float g_attn[M_TOTAL];                  // attention weights
__device__ float g_ctxpart[B_ * CTX_SPLIT * D_];   // partial contexts
__device__ unsigned short g_WhT_hi[(size_t)U_ * D_];  // bf16 hi of Wh^T [U][K]
__device__ unsigned short g_WhT_lo[(size_t)U_ * D_];  // bf16 residual

// split fp32 pair -> packed bf16 hi pair + residual pair
__device__ __forceinline__ void split2(float x, float y, unsigned& hi, unsigned& lo) {
    __nv_bfloat16 hx = __float2bfloat16_rn(x), hy = __float2bfloat16_rn(y);
    __nv_bfloat16 lx = __float2bfloat16_rn(x - __bfloat162float(hx));
    __nv_bfloat16 ly = __float2bfloat16_rn(y - __bfloat162float(hy));
    hi = (unsigned)__bfloat16_as_ushort(hx) | ((unsigned)__bfloat16_as_ushort(hy) << 16);
    lo = (unsigned)__bfloat16_as_ushort(lx) | ((unsigned)__bfloat16_as_ushort(ly) << 16);
}

// m16n8k16 row.col bf16 MMA, fp32 accumulate (sm_80+ family-wide PTX)
__device__ __forceinline__ void mma16816(float* c, const unsigned* a, const unsigned* b) {
    asm volatile(
        "mma.sync.aligned.m16n8k16.row.col.f32.bf16.bf16.f32 "
        "{%0,%1,%2,%3}, {%4,%5,%6,%7}, {%8,%9}, {%0,%1,%2,%3};"
        : "+f"(c[0]), "+f"(c[1]), "+f"(c[2]), "+f"(c[3])
        : "r"(a[0]), "r"(a[1]), "r"(a[2]), "r"(a[3]), "r"(b[0]), "r"(b[1]));
}

__device__ __forceinline__ float tanh_fast(float x) {
    // tanh(x) = 1 - 2/(exp(2x)+1); MUFU-based, ~1e-6 abs err, correct at +-inf
    return 1.f - __fdividef(2.f, __expf(2.f * x) + 1.f);
}

// ---------------- K0b: transpose + split Wh -> WhT hi/lo [U][K] ----------------
__global__ void k0b_split_whT(const float* __restrict__ Wh) {
    __shared__ float tt[32][33];
    const int k0 = blockIdx.y * 32, u0 = blockIdx.x * 32;
    for (int i = threadIdx.y; i < 32; i += 8)
        tt[i][threadIdx.x] = Wh[(size_t)(k0 + i) * U_ + u0 + threadIdx.x];
    __syncthreads();
    for (int i = threadIdx.y; i < 32; i += 8) {
        float v = tt[threadIdx.x][i];   // Wh[k0+tx][u0+i] -> WhT[u0+i][k0+tx]
        __nv_bfloat16 h = __float2bfloat16_rn(v);
        __nv_bfloat16 l = __float2bfloat16_rn(v - __bfloat162float(h));
        g_WhT_hi[(size_t)(u0 + i) * D_ + k0 + threadIdx.x] = __bfloat16_as_ushort(h);
        g_WhT_lo[(size_t)(u0 + i) * D_ + k0 + threadIdx.x] = __bfloat16_as_ushort(l);
    }
}

// ---------------- K1: base[b,u] = dec_hidden[b]@Ws[:,u] + bs+bh+bc ----------------
__global__ void k1_base(const float* __restrict__ dec, const float* __restrict__ Ws,
                        const float* __restrict__ bs, const float* __restrict__ bh,
                        const float* __restrict__ bc) {
    const int b = blockIdx.x, u = threadIdx.x;
    const float* dh = dec + b * D_;
    float acc = 0.f;
    #pragma unroll 8
    for (int d = 0; d < D_; ++d) acc = fmaf(dh[d], Ws[d * U_ + u], acc);
    g_base[b * U_ + u] = acc + bs[u] + bh[u] + bc[u];
}

// ---------------- K2: split-bf16 mma.sync GEMM + tanh + Vw reduction -> score ----------------
// CTA: 128 M-rows x (4 chunks of 128 U). 8 warps: warp w owns rows w*16..w*16+15, all 128 cols.
// K loop: 16 chunks of KC=32, double-buffered smem, register prefetch.
// 3 passes per k16: Ah*Bh + Al*Bh + Ah*Bl  (fp32 accum; rel err ~1.5e-5).
#define BM 128
#define BN 128
#define KC 32
#define RS 40                             /* smem row stride in u16: bank-conflict-free */
#define A_HALF_U16 (128 * RS)             /* 5120 u16 per half (A hi | A lo | B hi | B lo) */
#define STAGE_U16  (4 * A_HALF_U16)       /* 20480 u16 = 40960 B per stage */
#define K2_SMEM_BYTES (2 * STAGE_U16 * 2 + 3 * U_ * 4)   /* 81920 + 6144 = 88064 */

__global__ __launch_bounds__(256) void k2_score(
    const float* __restrict__ enc,   // (B*S, D) fp32
    const float* __restrict__ Wc,    // (1,U)
    const float* __restrict__ Vw,    // (U,1)
    const float* __restrict__ pcov)  // (B*S)
{
    extern __shared__ unsigned short sm16[];
    float* cf_base = (float*)(sm16 + 2 * STAGE_U16);
    float* cf_wc   = cf_base + U_;
    float* cf_vw   = cf_wc + U_;

    const int tid  = threadIdx.x;
    const int wid  = tid >> 5;
    const int lane = tid & 31;
    const int g    = lane >> 2;     // group id 0..7 (row within m16 tile)
    const int t    = lane & 3;      // thread-in-group 0..3 (k/col pairs)
    const int row0 = blockIdx.x * BM;
    const int b    = row0 / S_;
    const int rw   = wid * 16;      // warp's row base within the CTA tile

    // stage coefficients once
    for (int u = tid; u < U_; u += 256) {
        cf_base[u] = g_base[b * U_ + u];
        cf_wc[u]   = Wc[u];
        cf_vw[u]   = Vw[u];
    }

    const float pc_g  = pcov[row0 + rw + g];
    const float pc_g8 = pcov[row0 + rw + g + 8];
    float sc_g = 0.f, sc_g8 = 0.f;

    // staging coordinates (fixed): A: 2 threads/row, 4 float4 each; B: 2 threads/n-row, 2 int4/half
    const int ar = tid >> 1, ah = (tid & 1) * 16;   // A row, k-half offset
    const int bn = tid >> 1, bp = (tid & 1) * 16;   // B n-row, k-part offset
    const int aoff = ar * RS + ah;
    const int boff = bn * RS + bp;

    float4 ra[4];
    int4 rbh[2], rbl[2];

    __syncthreads();   // cf_* visible

    for (int nc = 0; nc < U_; nc += BN) {
        float acc[16][4];
        #pragma unroll
        for (int nt = 0; nt < 16; ++nt)
            #pragma unroll
            for (int i = 0; i < 4; ++i) acc[nt][i] = 0.f;

        // ---- prologue: load k-chunk 0, stage into buffer 0 ----
        #pragma unroll
        for (int i = 0; i < 4; ++i)
            ra[i] = *(const float4*)(enc + (size_t)(row0 + ar) * D_ + ah + i * 4);
        #pragma unroll
        for (int j = 0; j < 2; ++j) {
            rbh[j] = *(const int4*)(g_WhT_hi + (size_t)(nc + bn) * D_ + bp + j * 8);
            rbl[j] = *(const int4*)(g_WhT_lo + (size_t)(nc + bn) * D_ + bp + j * 8);
        }
        {
            unsigned short* Ah = sm16;
            unsigned short* Al = Ah + A_HALF_U16;
            unsigned short* Bh = Ah + 2 * A_HALF_U16;
            unsigned short* Bl = Ah + 3 * A_HALF_U16;
            #pragma unroll
            for (int i = 0; i < 4; ++i) {
                unsigned h01, l01, h23, l23;
                split2(ra[i].x, ra[i].y, h01, l01);
                split2(ra[i].z, ra[i].w, h23, l23);
                *(unsigned*)(Ah + aoff + i * 4)     = h01;
                *(unsigned*)(Ah + aoff + i * 4 + 2) = h23;
                *(unsigned*)(Al + aoff + i * 4)     = l01;
                *(unsigned*)(Al + aoff + i * 4 + 2) = l23;
            }
            #pragma unroll
            for (int j = 0; j < 2; ++j) {
                *(int4*)(Bh + boff + j * 8) = rbh[j];
                *(int4*)(Bl + boff + j * 8) = rbl[j];
            }
        }
        __syncthreads();

        int p = 0;
        for (int kc = 1; kc <= 16; ++kc) {
            // prefetch next chunk into registers (hidden under mma)
            if (kc < 16) {
                const int kg = kc * KC;
                #pragma unroll
                for (int i = 0; i < 4; ++i)
                    ra[i] = *(const float4*)(enc + (size_t)(row0 + ar) * D_ + kg + ah + i * 4);
                #pragma unroll
                for (int j = 0; j < 2; ++j) {
                    rbh[j] = *(const int4*)(g_WhT_hi + (size_t)(nc + bn) * D_ + kg + bp + j * 8);
                    rbl[j] = *(const int4*)(g_WhT_lo + (size_t)(nc + bn) * D_ + kg + bp + j * 8);
                }
            }

            // compute on buffer p
            {
                const unsigned short* Ah = sm16 + p * STAGE_U16;
                const unsigned short* Al = Ah + A_HALF_U16;
                const unsigned short* Bh = Ah + 2 * A_HALF_U16;
                const unsigned short* Bl = Ah + 3 * A_HALF_U16;
                #pragma unroll
                for (int k16 = 0; k16 < KC; k16 += 16) {
                    const int ao = (rw + g) * RS + k16 + t * 2;
                    unsigned afh[4], afl[4];
                    afh[0] = *(const unsigned*)(Ah + ao);
                    afh[1] = *(const unsigned*)(Ah + ao + 8 * RS);
                    afh[2] = *(const unsigned*)(Ah + ao + 8);
                    afh[3] = *(const unsigned*)(Ah + ao + 8 * RS + 8);
                    afl[0] = *(const unsigned*)(Al + ao);
                    afl[1] = *(const unsigned*)(Al + ao + 8 * RS);
                    afl[2] = *(const unsigned*)(Al + ao + 8);
                    afl[3] = *(const unsigned*)(Al + ao + 8 * RS + 8);
                    #pragma unroll
                    for (int nt = 0; nt < 16; ++nt) {
                        const int bo = (nt * 8 + g) * RS + k16 + t * 2;
                        unsigned bfh[2], bfl[2];
                        bfh[0] = *(const unsigned*)(Bh + bo);
                        bfh[1] = *(const unsigned*)(Bh + bo + 8);
                        bfl[0] = *(const unsigned*)(Bl + bo);
                        bfl[1] = *(const unsigned*)(Bl + bo + 8);
                        mma16816(acc[nt], afh, bfh);   // hi*hi
                        mma16816(acc[nt], afl, bfh);   // lo*hi
                        mma16816(acc[nt], afh, bfl);   // hi*lo
                    }
                }
            }

            // stage prefetched chunk into the other buffer
            if (kc < 16) {
                unsigned short* Ah = sm16 + (p ^ 1) * STAGE_U16;
                unsigned short* Al = Ah + A_HALF_U16;
                unsigned short* Bh = Ah + 2 * A_HALF_U16;
                unsigned short* Bl = Ah + 3 * A_HALF_U16;
                #pragma unroll
                for (int i = 0; i < 4; ++i) {
                    unsigned h01, l01, h23, l23;
                    split2(ra[i].x, ra[i].y, h01, l01);
                    split2(ra[i].z, ra[i].w, h23, l23);
                    *(unsigned*)(Ah + aoff + i * 4)     = h01;
                    *(unsigned*)(Ah + aoff + i * 4 + 2) = h23;
                    *(unsigned*)(Al + aoff + i * 4)     = l01;
                    *(unsigned*)(Al + aoff + i * 4 + 2) = l23;
                }
                #pragma unroll
                for (int j = 0; j < 2; ++j) {
                    *(int4*)(Bh + boff + j * 8) = rbh[j];
                    *(int4*)(Bl + boff + j * 8) = rbl[j];
                }
                __syncthreads();
                p ^= 1;
            }
        }

        // epilogue for this 128-wide u-chunk: tanh + Vw reduction
        #pragma unroll
        for (int nt = 0; nt < 16; ++nt) {
            const int u0 = nc + nt * 8 + t * 2;
            const int u1 = u0 + 1;
            const float b0v = cf_base[u0], b1v = cf_base[u1];
            const float w0 = cf_wc[u0],   w1 = cf_wc[u1];
            const float v0 = cf_vw[u0],   v1 = cf_vw[u1];
            sc_g  += v0 * tanh_fast(acc[nt][0] + b0v + pc_g  * w0);
            sc_g  += v1 * tanh_fast(acc[nt][1] + b1v + pc_g  * w1);
            sc_g8 += v0 * tanh_fast(acc[nt][2] + b0v + pc_g8 * w0);
            sc_g8 += v1 * tanh_fast(acc[nt][3] + b1v + pc_g8 * w1);
        }
        // separate this nc-iteration's buffer-0 use from the next prologue's stores
        __syncthreads();
    }

    // reduce over the 4 lanes of each group (t bits: xor 1, 2)
    sc_g  += __shfl_xor_sync(0xffffffffu, sc_g, 1);
    sc_g  += __shfl_xor_sync(0xffffffffu, sc_g, 2);
    sc_g8 += __shfl_xor_sync(0xffffffffu, sc_g8, 1);
    sc_g8 += __shfl_xor_sync(0xffffffffu, sc_g8, 2);
    if (t == 0) {
        g_score[row0 + rw + g]     = sc_g;
        g_score[row0 + rw + g + 8] = sc_g8;
    }
}

// ---------------- K3: masked renormalized softmax + coverage ----------------
__global__ __launch_bounds__(256) void k3_softmax(
    const float* __restrict__ mask, const float* __restrict__ pcov,
    float* __restrict__ out_attn, float* __restrict__ out_cov)
{
    const int b = blockIdx.x;
    const int tid = threadIdx.x;
    __shared__ float smax[8], ssum[8], sbc[2];

    float v[8];
    float mx = -3.0e38f;
    #pragma unroll
    for (int i = 0; i < 8; ++i) {
        v[i] = g_score[b * S_ + tid + i * 256];
        mx = fmaxf(mx, v[i]);
    }
    #pragma unroll
    for (int o = 16; o; o >>= 1) mx = fmaxf(mx, __shfl_xor_sync(0xffffffffu, mx, o));
    if ((tid & 31) == 0) smax[tid >> 5] = mx;
    __syncthreads();
    if (tid == 0) {
        float m = smax[0];
        #pragma unroll
        for (int w = 1; w < 8; ++w) m = fmaxf(m, smax[w]);
        sbc[0] = m;
    }
    __syncthreads();
    mx = sbc[0];

    float se = 0.f;
    #pragma unroll
    for (int i = 0; i < 8; ++i) {
        int idx = b * S_ + tid + i * 256;
        v[i] = __expf(v[i] - mx) * mask[idx];
        se += v[i];
    }
    #pragma unroll
    for (int o = 16; o; o >>= 1) se += __shfl_xor_sync(0xffffffffu, se, o);
    if ((tid & 31) == 0) ssum[tid >> 5] = se;
    __syncthreads();
    if (tid == 0) {
        float s2 = ssum[0];
        #pragma unroll
        for (int w = 1; w < 8; ++w) s2 += ssum[w];
        sbc[1] = 1.f / s2;
    }
    __syncthreads();
    const float inv = sbc[1];

    #pragma unroll
    for (int i = 0; i < 8; ++i) {
        int idx = b * S_ + tid + i * 256;
        float a = v[i] * inv;
        g_attn[idx]   = a;
        out_attn[idx] = a;
        out_cov[idx]  = a + pcov[idx];
    }
}

// ---------------- K4: partial context over S-chunks ----------------
__global__ __launch_bounds__(128) void k4_ctx(const float* __restrict__ enc)
{
    const int chunk = blockIdx.x, b = blockIdx.y, tid = threadIdx.x;
    __shared__ float at[S_ / CTX_SPLIT];
    const int s0 = chunk * (S_ / CTX_SPLIT);
    for (int i = tid; i < S_ / CTX_SPLIT; i += 128)
        at[i] = g_attn[b * S_ + s0 + i];
    __syncthreads();

    float4 acc = make_float4(0.f, 0.f, 0.f, 0.f);
    const float* base = enc + ((size_t)b * S_ + s0) * D_ + tid * 4;
    #pragma unroll 4
    for (int s = 0; s < S_ / CTX_SPLIT; ++s) {
        float a = at[s];
        float4 e = *(const float4*)(base + (size_t)s * D_);
        acc.x = fmaf(a, e.x, acc.x);
        acc.y = fmaf(a, e.y, acc.y);
        acc.z = fmaf(a, e.z, acc.z);
        acc.w = fmaf(a, e.w, acc.w);
    }
    *(float4*)&g_ctxpart[((size_t)b * CTX_SPLIT + chunk) * D_ + tid * 4] = acc;
}

// ---------------- K5: reduce partial contexts ----------------
__global__ void k5_ctxred(float* __restrict__ out_ctx)
{
    const int b = blockIdx.x, d = threadIdx.x;
    float s = 0.f;
    #pragma unroll
    for (int c = 0; c < CTX_SPLIT; ++c)
        s += g_ctxpart[((size_t)b * CTX_SPLIT + c) * D_ + d];
    out_ctx[b * D_ + d] = s;
}

// ---------------- launcher ----------------
extern "C" void kernel_launch(void* const* d_in, const int* in_sizes, int n_in,
                              void* d_out, int out_size)
{
    const float* dec  = (const float*)d_in[0];   // (B,D)
    const float* enc  = (const float*)d_in[1];   // (B,S,D)
    const float* mask = (const float*)d_in[2];   // (B,S)
    const float* pcov = (const float*)d_in[3];   // (B,S,1)
    const float* Wh   = (const float*)d_in[4];   // (D,U)
    const float* bh   = (const float*)d_in[5];   // (U)
    const float* Ws   = (const float*)d_in[6];   // (D,U)
    const float* bs   = (const float*)d_in[7];   // (U)
    const float* Wc   = (const float*)d_in[8];   // (1,U)
    const float* bc   = (const float*)d_in[9];   // (U)
    const float* Vw   = (const float*)d_in[10];  // (U,1)
    // d_in[11] = bv: shift-invariant under softmax, unused.

    float* out_ctx  = (float*)d_out;             // (B,D)
    float* out_attn = out_ctx + B_ * D_;         // (B,S)
    float* out_cov  = out_attn + B_ * S_;        // (B,S,1)

    // attribute set: not a stream op, not an alloc; capture-safe and idempotent
    cudaFuncSetAttribute(k2_score, cudaFuncAttributeMaxDynamicSharedMemorySize,
                         K2_SMEM_BYTES);

    k0b_split_whT<<<dim3(U_ / 32, D_ / 32), dim3(32, 8)>>>(Wh);
    k1_base<<<B_, U_>>>(dec, Ws, bs, bh, bc);
    k2_score<<<M_TOTAL / BM, 256, K2_SMEM_BYTES>>>(enc, Wc, Vw, pcov);
    k3_softmax<<<B_, 256>>>(mask, pcov, out_attn, out_cov);
    k4_ctx<<<dim3(CTX_SPLIT, B_), 128>>>(enc);
    k5_ctxred<<<B_, D_>>>(out_ctx);
}